// round 1
// baseline (speedup 1.0000x reference)
#include <cuda_runtime.h>
#include <cuda_bf16.h>
#include <mma.h>

using namespace nvcuda;

// Problem constants
#define LNUM 4
#define BDIM 128
#define INDIM 512
#define CTXDIM 512
#define STDIM 512
#define DDIM 1536
#define RDIM 256
#define CDIM 256

// Scratch (device globals: no allocation allowed)
__device__ float g_G[LNUM * BDIM * 1536];   // raw phi|alpha|beta pre-activations (3 MB)
__device__ float g_UV[LNUM * BDIM * 512];   // raw u|v (biases added at use site)   (1 MB)

__device__ __forceinline__ float sigf(float v) { return 1.0f / (1.0f + expf(-v)); }

// ---------------------------------------------------------------------------
// GEMM 1: G[l][b][n] = sum_d gi[l,b,d] * W_n[d],  n in [0,1536)
//   gi = [x | c | h[l]] gathered on the fly (each 32-wide K chunk lies in one segment)
//   W  = phi_w (n<512) | alpha_w | beta_w, each (512,1536) row-major per level
// CTA tile 128(M=B) x 64(N), K=1536 chunked by 32, tf32 WMMA m16n16k8.
// grid: (24 n-tiles, 4 levels), 256 threads (8 warps, 4x2 warp grid, 32x32 warp tile)
// ---------------------------------------------------------------------------
__global__ void __launch_bounds__(256) gemm_gate(
    const float* __restrict__ x, const float* __restrict__ c, const float* __restrict__ h,
    const float* __restrict__ phi_w, const float* __restrict__ alpha_w,
    const float* __restrict__ beta_w)
{
    __shared__ __align__(16) float As[128][36];
    __shared__ __align__(16) float Ws[64][36];

    const int l  = blockIdx.y;
    const int n0 = blockIdx.x * 64;
    const int tid = threadIdx.x;
    const int warp = tid >> 5;
    const int wm = warp & 3;       // 0..3  (32-row block)
    const int wn = warp >> 2;      // 0..1  (32-col block)

    const float* Wp;
    {
        int seg = n0 >> 9;  // 0:phi 1:alpha 2:beta
        const float* wsrc = (seg == 0) ? phi_w : (seg == 1) ? alpha_w : beta_w;
        Wp = wsrc + (size_t)l * 512 * 1536 + (size_t)(n0 & 511) * 1536;
    }

    wmma::fragment<wmma::accumulator, 16, 16, 8, float> acc[2][2];
#pragma unroll
    for (int i = 0; i < 2; i++)
#pragma unroll
        for (int j = 0; j < 2; j++) wmma::fill_fragment(acc[i][j], 0.0f);

    const int arow = tid >> 3;        // 0..31
    const int acol = (tid & 7) * 4;   // 0..28
    const int wrow = tid >> 2;        // 0..63
    const int wcol = (tid & 3) * 4;   // 0..12

    for (int k0 = 0; k0 < 1536; k0 += 32) {
        // stage A (gathered gi), tf32-rounded
        const float* abase;
        if (k0 < 512)       abase = x + k0;
        else if (k0 < 1024) abase = c + (k0 - 512);
        else                abase = h + (size_t)l * BDIM * STDIM + (k0 - 1024);
#pragma unroll
        for (int i = 0; i < 4; i++) {
            int row = arow + i * 32;
            float4 v = *reinterpret_cast<const float4*>(abase + (size_t)row * 512 + acol);
            As[row][acol + 0] = wmma::__float_to_tf32(v.x);
            As[row][acol + 1] = wmma::__float_to_tf32(v.y);
            As[row][acol + 2] = wmma::__float_to_tf32(v.z);
            As[row][acol + 3] = wmma::__float_to_tf32(v.w);
        }
        // stage W, tf32-rounded
#pragma unroll
        for (int j = 0; j < 2; j++) {
            int col = wcol + j * 16;
            float4 v = *reinterpret_cast<const float4*>(Wp + (size_t)wrow * 1536 + k0 + col);
            Ws[wrow][col + 0] = wmma::__float_to_tf32(v.x);
            Ws[wrow][col + 1] = wmma::__float_to_tf32(v.y);
            Ws[wrow][col + 2] = wmma::__float_to_tf32(v.z);
            Ws[wrow][col + 3] = wmma::__float_to_tf32(v.w);
        }
        __syncthreads();

#pragma unroll
        for (int kk = 0; kk < 32; kk += 8) {
            wmma::fragment<wmma::matrix_a, 16, 16, 8, wmma::precision::tf32, wmma::row_major> af[2];
            wmma::fragment<wmma::matrix_b, 16, 16, 8, wmma::precision::tf32, wmma::col_major> bf[2];
#pragma unroll
            for (int i = 0; i < 2; i++) wmma::load_matrix_sync(af[i], &As[wm * 32 + i * 16][kk], 36);
#pragma unroll
            for (int j = 0; j < 2; j++) wmma::load_matrix_sync(bf[j], &Ws[wn * 32 + j * 16][kk], 36);
#pragma unroll
            for (int i = 0; i < 2; i++)
#pragma unroll
                for (int j = 0; j < 2; j++)
                    wmma::mma_sync(acc[i][j], af[i], bf[j], acc[i][j]);
        }
        __syncthreads();
    }

    float* C = g_G + (size_t)l * BDIM * 1536;
#pragma unroll
    for (int i = 0; i < 2; i++)
#pragma unroll
        for (int j = 0; j < 2; j++)
            wmma::store_matrix_sync(&C[(size_t)(wm * 32 + i * 16) * 1536 + n0 + wn * 32 + j * 16],
                                    acc[i][j], 1536, wmma::mem_row_major);
}

// ---------------------------------------------------------------------------
// Gate epilogue: h_new = sigmoid(alpha)*tanh(phi) + sigmoid(beta)*h  -> d_out[0:262144]
// ---------------------------------------------------------------------------
__global__ void __launch_bounds__(256) gate_epi(
    const float* __restrict__ h,
    const float* __restrict__ phi_b, const float* __restrict__ alpha_b,
    const float* __restrict__ beta_b, float* __restrict__ out)
{
    int idx = blockIdx.x * 256 + threadIdx.x;     // < 65536
    int o = (idx & 127) << 2;                     // 0..508
    int b = (idx >> 7) & 127;
    int l = idx >> 14;

    size_t gbase = ((size_t)l * BDIM + b) * 1536;
    float4 ph = *reinterpret_cast<const float4*>(g_G + gbase + o);
    float4 av = *reinterpret_cast<const float4*>(g_G + gbase + 512 + o);
    float4 bv = *reinterpret_cast<const float4*>(g_G + gbase + 1024 + o);
    float4 pb = *reinterpret_cast<const float4*>(phi_b + l * 512 + o);
    float4 ab = *reinterpret_cast<const float4*>(alpha_b + l * 512 + o);
    float4 bb = *reinterpret_cast<const float4*>(beta_b + l * 512 + o);
    size_t hoff = ((size_t)l * BDIM + b) * STDIM + o;
    float4 hv = *reinterpret_cast<const float4*>(h + hoff);

    float4 r;
    r.x = sigf(av.x + ab.x) * tanhf(ph.x + pb.x) + sigf(bv.x + bb.x) * hv.x;
    r.y = sigf(av.y + ab.y) * tanhf(ph.y + pb.y) + sigf(bv.y + bb.y) * hv.y;
    r.z = sigf(av.z + ab.z) * tanhf(ph.z + pb.z) + sigf(bv.z + bb.z) * hv.z;
    r.w = sigf(av.w + ab.w) * tanhf(ph.w + pb.w) + sigf(bv.w + bb.w) * hv.w;
    *reinterpret_cast<float4*>(out + hoff) = r;
}

// ---------------------------------------------------------------------------
// GEMM 2: UV[l][b][n] = sum_d wv[l,b,d] * W_n[d],  n in [0,512): u(0..255)|v(256..511)
//   wv = [h_new | x | c] gathered on the fly (h_new read from d_out)
// grid: (8 n-tiles, 4 levels)
// ---------------------------------------------------------------------------
__global__ void __launch_bounds__(256) gemm_uv(
    const float* __restrict__ hn, const float* __restrict__ x, const float* __restrict__ c,
    const float* __restrict__ u_w, const float* __restrict__ v_w)
{
    __shared__ __align__(16) float As[128][36];
    __shared__ __align__(16) float Ws[64][36];

    const int l  = blockIdx.y;
    const int n0 = blockIdx.x * 64;
    const int tid = threadIdx.x;
    const int warp = tid >> 5;
    const int wm = warp & 3;
    const int wn = warp >> 2;

    const float* Wp;
    {
        int seg = n0 >> 8;  // 0:u 1:v
        const float* wsrc = seg ? v_w : u_w;
        Wp = wsrc + (size_t)l * 256 * 1536 + (size_t)(n0 & 255) * 1536;
    }

    wmma::fragment<wmma::accumulator, 16, 16, 8, float> acc[2][2];
#pragma unroll
    for (int i = 0; i < 2; i++)
#pragma unroll
        for (int j = 0; j < 2; j++) wmma::fill_fragment(acc[i][j], 0.0f);

    const int arow = tid >> 3;
    const int acol = (tid & 7) * 4;
    const int wrow = tid >> 2;
    const int wcol = (tid & 3) * 4;

    for (int k0 = 0; k0 < 1536; k0 += 32) {
        const float* abase;
        if (k0 < 512)       abase = hn + (size_t)l * BDIM * STDIM + k0;
        else if (k0 < 1024) abase = x + (k0 - 512);
        else                abase = c + (k0 - 1024);
#pragma unroll
        for (int i = 0; i < 4; i++) {
            int row = arow + i * 32;
            float4 v = *reinterpret_cast<const float4*>(abase + (size_t)row * 512 + acol);
            As[row][acol + 0] = wmma::__float_to_tf32(v.x);
            As[row][acol + 1] = wmma::__float_to_tf32(v.y);
            As[row][acol + 2] = wmma::__float_to_tf32(v.z);
            As[row][acol + 3] = wmma::__float_to_tf32(v.w);
        }
#pragma unroll
        for (int j = 0; j < 2; j++) {
            int col = wcol + j * 16;
            float4 v = *reinterpret_cast<const float4*>(Wp + (size_t)wrow * 1536 + k0 + col);
            Ws[wrow][col + 0] = wmma::__float_to_tf32(v.x);
            Ws[wrow][col + 1] = wmma::__float_to_tf32(v.y);
            Ws[wrow][col + 2] = wmma::__float_to_tf32(v.z);
            Ws[wrow][col + 3] = wmma::__float_to_tf32(v.w);
        }
        __syncthreads();

#pragma unroll
        for (int kk = 0; kk < 32; kk += 8) {
            wmma::fragment<wmma::matrix_a, 16, 16, 8, wmma::precision::tf32, wmma::row_major> af[2];
            wmma::fragment<wmma::matrix_b, 16, 16, 8, wmma::precision::tf32, wmma::col_major> bf[2];
#pragma unroll
            for (int i = 0; i < 2; i++) wmma::load_matrix_sync(af[i], &As[wm * 32 + i * 16][kk], 36);
#pragma unroll
            for (int j = 0; j < 2; j++) wmma::load_matrix_sync(bf[j], &Ws[wn * 32 + j * 16][kk], 36);
#pragma unroll
            for (int i = 0; i < 2; i++)
#pragma unroll
                for (int j = 0; j < 2; j++)
                    wmma::mma_sync(acc[i][j], af[i], bf[j], acc[i][j]);
        }
        __syncthreads();
    }

    float* C = g_UV + (size_t)l * BDIM * 512;
#pragma unroll
    for (int i = 0; i < 2; i++)
#pragma unroll
        for (int j = 0; j < 2; j++)
            wmma::store_matrix_sync(&C[(size_t)(wm * 32 + i * 16) * 512 + n0 + wn * 32 + j * 16],
                                    acc[i][j], 512, wmma::mem_row_major);
}

// ---------------------------------------------------------------------------
// M update: M_new[l] = (1-g)M[l] + 0.5 g (M[up]+M[dn]) + e * u[l] v[l]^T
// All 4 levels at fixed (b,r,c) handled by one thread -> each M element read once.
// ---------------------------------------------------------------------------
__global__ void __launch_bounds__(256) m_update(
    const float* __restrict__ M, const float* __restrict__ u_b, const float* __restrict__ v_b,
    const float* __restrict__ gl, const float* __restrict__ el, float* __restrict__ out)
{
    int idx = blockIdx.x * 256 + threadIdx.x;   // < 2097152
    int cc = (idx & 63) << 2;                   // c = cc..cc+3
    int r  = (idx >> 6) & 255;
    int b  = idx >> 14;
    const size_t LS = (size_t)BDIM * RDIM * CDIM;   // 8388608
    size_t moff = ((size_t)b * RDIM + r) * CDIM + cc;

    float4 m0 = *reinterpret_cast<const float4*>(M + 0 * LS + moff);
    float4 m1 = *reinterpret_cast<const float4*>(M + 1 * LS + moff);
    float4 m2 = *reinterpret_cast<const float4*>(M + 2 * LS + moff);
    float4 m3 = *reinterpret_cast<const float4*>(M + 3 * LS + moff);

    float* outM = out + (size_t)LNUM * BDIM * STDIM;  // after h_new block

#pragma unroll
    for (int l = 0; l < 4; l++) {
        float g = sigf(gl[l]);
        float e = sigf(el[l]);
        float u = g_UV[(size_t)l * 65536 + b * 512 + r] + u_b[l * 256 + r];
        float4 vv  = *reinterpret_cast<const float4*>(g_UV + (size_t)l * 65536 + b * 512 + 256 + cc);
        float4 vbv = *reinterpret_cast<const float4*>(v_b + l * 256 + cc);
        vv.x += vbv.x; vv.y += vbv.y; vv.z += vbv.z; vv.w += vbv.w;

        float4 ml = (l == 0) ? m0 : (l == 1) ? m1 : (l == 2) ? m2 : m3;
        float4 mu = (l == 0) ? m0 : (l == 1) ? m0 : (l == 2) ? m1 : m2;
        float4 md = (l == 0) ? m1 : (l == 1) ? m2 : (l == 2) ? m3 : m3;

        float omg = 1.0f - g;
        float gh  = 0.5f * g;
        float eu  = e * u;
        float4 o;
        o.x = omg * ml.x + gh * (mu.x + md.x) + eu * vv.x;
        o.y = omg * ml.y + gh * (mu.y + md.y) + eu * vv.y;
        o.z = omg * ml.z + gh * (mu.z + md.z) + eu * vv.z;
        o.w = omg * ml.w + gh * (mu.w + md.w) + eu * vv.w;
        *reinterpret_cast<float4*>(outM + (size_t)l * LS + moff) = o;
    }
}

// ---------------------------------------------------------------------------
extern "C" void kernel_launch(void* const* d_in, const int* in_sizes, int n_in,
                              void* d_out, int out_size)
{
    const float* x        = (const float*)d_in[0];
    const float* c        = (const float*)d_in[1];
    const float* h        = (const float*)d_in[2];
    const float* M        = (const float*)d_in[3];
    const float* phi_w    = (const float*)d_in[4];
    const float* phi_b    = (const float*)d_in[5];
    const float* alpha_w  = (const float*)d_in[6];
    const float* alpha_b  = (const float*)d_in[7];
    const float* beta_w   = (const float*)d_in[8];
    const float* beta_b   = (const float*)d_in[9];
    const float* u_w      = (const float*)d_in[10];
    const float* u_b      = (const float*)d_in[11];
    const float* v_w      = (const float*)d_in[12];
    const float* v_b      = (const float*)d_in[13];
    const float* gamma_l  = (const float*)d_in[14];
    const float* eta_l    = (const float*)d_in[15];
    float* out = (float*)d_out;

    // 1) gate GEMM: phi|alpha|beta pre-activations
    gemm_gate<<<dim3(24, 4), 256>>>(x, c, h, phi_w, alpha_w, beta_w);
    // 2) h_new into d_out[0 : L*B*ST)
    gate_epi<<<256, 256>>>(h, phi_b, alpha_b, beta_b, out);
    // 3) u|v GEMM (reads h_new from d_out)
    gemm_uv<<<dim3(8, 4), 256>>>(out, x, c, u_w, v_w);
    // 4) M_new into d_out[L*B*ST : end)
    m_update<<<8192, 256>>>(M, u_b, v_b, gamma_l, eta_l, out);
}

// round 4
// speedup vs baseline: 1.8366x; 1.8366x over previous
#include <cuda_runtime.h>
#include <cuda_bf16.h>
#include <mma.h>

using namespace nvcuda;

#define LNUM 4
#define BDIM 128
#define STDIM 512
#define RDIM 256
#define CDIM 256
#define KSPLIT 4

// Scratch (device globals: no allocation allowed)
__device__ float g_G4[KSPLIT][LNUM * BDIM * 1536];  // partial phi|alpha|beta (12.6 MB)
__device__ float g_UV4[KSPLIT][LNUM * BDIM * 512];  // partial u|v (4 MB)
__device__ float g_UV[LNUM * BDIM * 512];           // reduced u|v (1 MB)

__device__ __forceinline__ float sigf(float v) { return 1.0f / (1.0f + expf(-v)); }

// ---------------------------------------------------------------------------
// GEMM 1 (K-split): G4[ks][l][b][n] = sum_{d in ks-range} gi[l,b,d] * W_n[d]
// gi = [x|c|h[l]]. Tile 128x64, K chunk 16, 2-stage smem w/ register prefetch.
// grid (24, 4, 4): n-tile, level, K-split. 256 thr, 8 warps (4x2 of 32x32).
// ---------------------------------------------------------------------------
__global__ void __launch_bounds__(256) gemm_gate(
    const float* __restrict__ x, const float* __restrict__ c, const float* __restrict__ h,
    const float* __restrict__ phi_w, const float* __restrict__ alpha_w,
    const float* __restrict__ beta_w)
{
    __shared__ __align__(16) float As[2][128][20];
    __shared__ __align__(16) float Ws[2][64][20];

    const int l  = blockIdx.y;
    const int n0 = blockIdx.x * 64;
    const int ks = blockIdx.z;
    const int kbase = ks * 384;
    const int tid = threadIdx.x;
    const int warp = tid >> 5;
    const int wm = warp & 3;
    const int wn = warp >> 2;

    const float* Wp;
    {
        int seg = n0 >> 9;
        const float* wsrc = (seg == 0) ? phi_w : (seg == 1) ? alpha_w : beta_w;
        Wp = wsrc + (size_t)l * 512 * 1536 + (size_t)(n0 & 511) * 1536;
    }
    const float* hl = h + (size_t)l * BDIM * STDIM;

    wmma::fragment<wmma::accumulator, 16, 16, 8, float> acc[2][2];
#pragma unroll
    for (int i = 0; i < 2; i++)
#pragma unroll
        for (int j = 0; j < 2; j++) wmma::fill_fragment(acc[i][j], 0.0f);

    const int r_a = tid >> 1;            // 0..127
    const int ca  = (tid & 1) * 8;       // col 0 or 8
    const int r_w = tid >> 2;            // 0..63
    const int cw  = (tid & 3) * 4;       // col 0,4,8,12

    float4 pa0, pa1, pw;

    auto load_regs = [&](int k0) {
        const float* aseg; int ko;
        if (k0 < 512)       { aseg = x;  ko = k0; }
        else if (k0 < 1024) { aseg = c;  ko = k0 - 512; }
        else                { aseg = hl; ko = k0 - 1024; }
        const float* ga = aseg + (size_t)r_a * 512 + ko + ca;
        pa0 = *reinterpret_cast<const float4*>(ga);
        pa1 = *reinterpret_cast<const float4*>(ga + 4);
        pw  = *reinterpret_cast<const float4*>(Wp + (size_t)r_w * 1536 + k0 + cw);
    };
    auto store_smem = [&](int st) {
        *reinterpret_cast<float4*>(&As[st][r_a][ca])     = pa0;
        *reinterpret_cast<float4*>(&As[st][r_a][ca + 4]) = pa1;
        *reinterpret_cast<float4*>(&Ws[st][r_w][cw])     = pw;
    };

    load_regs(kbase);
    store_smem(0);

    for (int it = 0; it < 24; it++) {
        int st = it & 1;
        __syncthreads();
        if (it + 1 < 24) load_regs(kbase + (it + 1) * 16);

#pragma unroll
        for (int kk = 0; kk < 16; kk += 8) {
            wmma::fragment<wmma::matrix_a, 16, 16, 8, wmma::precision::tf32, wmma::row_major> af[2];
            wmma::fragment<wmma::matrix_b, 16, 16, 8, wmma::precision::tf32, wmma::col_major> bf[2];
#pragma unroll
            for (int i = 0; i < 2; i++) {
                wmma::load_matrix_sync(af[i], &As[st][wm * 32 + i * 16][kk], 20);
#pragma unroll
                for (int t = 0; t < af[i].num_elements; t++) af[i].x[t] = wmma::__float_to_tf32(af[i].x[t]);
            }
#pragma unroll
            for (int j = 0; j < 2; j++) {
                wmma::load_matrix_sync(bf[j], &Ws[st][wn * 32 + j * 16][kk], 20);
#pragma unroll
                for (int t = 0; t < bf[j].num_elements; t++) bf[j].x[t] = wmma::__float_to_tf32(bf[j].x[t]);
            }
#pragma unroll
            for (int i = 0; i < 2; i++)
#pragma unroll
                for (int j = 0; j < 2; j++)
                    wmma::mma_sync(acc[i][j], af[i], bf[j], acc[i][j]);
        }
        if (it + 1 < 24) store_smem(st ^ 1);
    }

    float* C = g_G4[ks] + (size_t)l * BDIM * 1536;
#pragma unroll
    for (int i = 0; i < 2; i++)
#pragma unroll
        for (int j = 0; j < 2; j++)
            wmma::store_matrix_sync(&C[(size_t)(wm * 32 + i * 16) * 1536 + n0 + wn * 32 + j * 16],
                                    acc[i][j], 1536, wmma::mem_row_major);
}

// ---------------------------------------------------------------------------
// Gate epilogue: reduce K-splits, h_new = sig(a)*tanh(p) + sig(b)*h -> d_out
// ---------------------------------------------------------------------------
__global__ void __launch_bounds__(256) gate_epi(
    const float* __restrict__ h,
    const float* __restrict__ phi_b, const float* __restrict__ alpha_b,
    const float* __restrict__ beta_b, float* __restrict__ out)
{
    int idx = blockIdx.x * 256 + threadIdx.x;     // < 65536
    int o = (idx & 127) << 2;
    int b = (idx >> 7) & 127;
    int l = idx >> 14;

    size_t gbase = ((size_t)l * BDIM + b) * 1536;
    float4 ph = make_float4(0.f, 0.f, 0.f, 0.f), av = ph, bv = ph;
#pragma unroll
    for (int ks = 0; ks < KSPLIT; ks++) {
        float4 p = *reinterpret_cast<const float4*>(g_G4[ks] + gbase + o);
        float4 a = *reinterpret_cast<const float4*>(g_G4[ks] + gbase + 512 + o);
        float4 bb2 = *reinterpret_cast<const float4*>(g_G4[ks] + gbase + 1024 + o);
        ph.x += p.x; ph.y += p.y; ph.z += p.z; ph.w += p.w;
        av.x += a.x; av.y += a.y; av.z += a.z; av.w += a.w;
        bv.x += bb2.x; bv.y += bb2.y; bv.z += bb2.z; bv.w += bb2.w;
    }
    float4 pb = *reinterpret_cast<const float4*>(phi_b + l * 512 + o);
    float4 ab = *reinterpret_cast<const float4*>(alpha_b + l * 512 + o);
    float4 bb = *reinterpret_cast<const float4*>(beta_b + l * 512 + o);
    size_t hoff = ((size_t)l * BDIM + b) * STDIM + o;
    float4 hv = *reinterpret_cast<const float4*>(h + hoff);

    float4 r;
    r.x = sigf(av.x + ab.x) * tanhf(ph.x + pb.x) + sigf(bv.x + bb.x) * hv.x;
    r.y = sigf(av.y + ab.y) * tanhf(ph.y + pb.y) + sigf(bv.y + bb.y) * hv.y;
    r.z = sigf(av.z + ab.z) * tanhf(ph.z + pb.z) + sigf(bv.z + bb.z) * hv.z;
    r.w = sigf(av.w + ab.w) * tanhf(ph.w + pb.w) + sigf(bv.w + bb.w) * hv.w;
    *reinterpret_cast<float4*>(out + hoff) = r;
}

// ---------------------------------------------------------------------------
// GEMM 2 (K-split): UV4[ks][l][b][n], n in [0,512): u|v.  wv = [h_new|x|c].
// Tile 128x32 (8 warps of 16x32), grid (16, 4, 4), 2-stage reg prefetch.
// ---------------------------------------------------------------------------
__global__ void __launch_bounds__(256) gemm_uv(
    const float* __restrict__ hn, const float* __restrict__ x, const float* __restrict__ c,
    const float* __restrict__ u_w, const float* __restrict__ v_w)
{
    __shared__ __align__(16) float As[2][128][20];
    __shared__ __align__(16) float Ws[2][32][20];

    const int l  = blockIdx.y;
    const int n0 = blockIdx.x * 32;
    const int ks = blockIdx.z;
    const int kbase = ks * 384;
    const int tid = threadIdx.x;
    const int warp = tid >> 5;   // 16-row block

    const float* Wp;
    {
        int seg = n0 >> 8;
        const float* wsrc = seg ? v_w : u_w;
        Wp = wsrc + (size_t)l * 256 * 1536 + (size_t)(n0 & 255) * 1536;
    }
    const float* hl = hn + (size_t)l * BDIM * STDIM;

    wmma::fragment<wmma::accumulator, 16, 16, 8, float> acc[2];
#pragma unroll
    for (int j = 0; j < 2; j++) wmma::fill_fragment(acc[j], 0.0f);

    const int r_a = tid >> 1;
    const int ca  = (tid & 1) * 8;
    const int r_w = tid >> 2;   // 0..31 valid for tid<128
    const int cw  = (tid & 3) * 4;

    float4 pa0, pa1, pw;

    auto load_regs = [&](int k0) {
        const float* aseg; int ko;
        if (k0 < 512)       { aseg = hl; ko = k0; }
        else if (k0 < 1024) { aseg = x;  ko = k0 - 512; }
        else                { aseg = c;  ko = k0 - 1024; }
        const float* ga = aseg + (size_t)r_a * 512 + ko + ca;
        pa0 = *reinterpret_cast<const float4*>(ga);
        pa1 = *reinterpret_cast<const float4*>(ga + 4);
        if (tid < 128) pw = *reinterpret_cast<const float4*>(Wp + (size_t)r_w * 1536 + k0 + cw);
    };
    auto store_smem = [&](int st) {
        *reinterpret_cast<float4*>(&As[st][r_a][ca])     = pa0;
        *reinterpret_cast<float4*>(&As[st][r_a][ca + 4]) = pa1;
        if (tid < 128) *reinterpret_cast<float4*>(&Ws[st][r_w][cw]) = pw;
    };

    load_regs(kbase);
    store_smem(0);

    for (int it = 0; it < 24; it++) {
        int st = it & 1;
        __syncthreads();
        if (it + 1 < 24) load_regs(kbase + (it + 1) * 16);

#pragma unroll
        for (int kk = 0; kk < 16; kk += 8) {
            wmma::fragment<wmma::matrix_a, 16, 16, 8, wmma::precision::tf32, wmma::row_major> af;
            wmma::fragment<wmma::matrix_b, 16, 16, 8, wmma::precision::tf32, wmma::col_major> bf[2];
            wmma::load_matrix_sync(af, &As[st][warp * 16][kk], 20);
#pragma unroll
            for (int t = 0; t < af.num_elements; t++) af.x[t] = wmma::__float_to_tf32(af.x[t]);
#pragma unroll
            for (int j = 0; j < 2; j++) {
                wmma::load_matrix_sync(bf[j], &Ws[st][j * 16][kk], 20);
#pragma unroll
                for (int t = 0; t < bf[j].num_elements; t++) bf[j].x[t] = wmma::__float_to_tf32(bf[j].x[t]);
            }
#pragma unroll
            for (int j = 0; j < 2; j++)
                wmma::mma_sync(acc[j], af, bf[j], acc[j]);
        }
        if (it + 1 < 24) store_smem(st ^ 1);
    }

    float* C = g_UV4[ks] + (size_t)l * BDIM * 512;
#pragma unroll
    for (int j = 0; j < 2; j++)
        wmma::store_matrix_sync(&C[(size_t)(warp * 16) * 512 + n0 + j * 16],
                                acc[j], 512, wmma::mem_row_major);
}

// ---------------------------------------------------------------------------
// Reduce UV K-splits: g_UV = sum_ks g_UV4[ks]
// ---------------------------------------------------------------------------
__global__ void __launch_bounds__(256) uv_reduce()
{
    int idx = blockIdx.x * 256 + threadIdx.x;   // < 65536 (float4 count)
    float4 s = make_float4(0.f, 0.f, 0.f, 0.f);
#pragma unroll
    for (int ks = 0; ks < KSPLIT; ks++) {
        float4 p = reinterpret_cast<const float4*>(g_UV4[ks])[idx];
        s.x += p.x; s.y += p.y; s.z += p.z; s.w += p.w;
    }
    reinterpret_cast<float4*>(g_UV)[idx] = s;
}

// ---------------------------------------------------------------------------
// M update: M_new[l] = (1-g)M[l] + 0.5 g (M[up]+M[dn]) + e * u[l] v[l]^T
// 8 floats (2x float4) per thread, all 4 levels in registers.
// ---------------------------------------------------------------------------
__global__ void __launch_bounds__(256) m_update(
    const float* __restrict__ M, const float* __restrict__ u_b, const float* __restrict__ v_b,
    const float* __restrict__ gl, const float* __restrict__ el, float* __restrict__ out)
{
    int idx = blockIdx.x * 256 + threadIdx.x;   // < 1048576
    int cc = (idx & 31) << 3;                   // c = cc..cc+7
    int r  = (idx >> 5) & 255;
    int b  = idx >> 13;
    const size_t LS = (size_t)BDIM * RDIM * CDIM;   // 8388608
    size_t moff = ((size_t)b * RDIM + r) * CDIM + cc;

    float4 m[4][2];
#pragma unroll
    for (int l = 0; l < 4; l++) {
        const float4* mp = reinterpret_cast<const float4*>(M + (size_t)l * LS + moff);
        m[l][0] = __ldcs(mp);
        m[l][1] = __ldcs(mp + 1);
    }

    float* outM = out + (size_t)LNUM * BDIM * STDIM;

#pragma unroll
    for (int l = 0; l < 4; l++) {
        float g = sigf(gl[l]);
        float e = sigf(el[l]);
        float u = g_UV[(size_t)l * 65536 + b * 512 + r] + u_b[l * 256 + r];
        const float4* vp  = reinterpret_cast<const float4*>(g_UV + (size_t)l * 65536 + b * 512 + 256 + cc);
        const float4* vbp = reinterpret_cast<const float4*>(v_b + l * 256 + cc);
        float4 vv[2];
#pragma unroll
        for (int p = 0; p < 2; p++) {
            float4 t = vp[p], tb = vbp[p];
            t.x += tb.x; t.y += tb.y; t.z += tb.z; t.w += tb.w;
            vv[p] = t;
        }
        const int up = (l == 0) ? 0 : l - 1;
        const int dn = (l == 3) ? 3 : l + 1;
        float omg = 1.0f - g;
        float gh  = 0.5f * g;
        float eu  = e * u;
        float4* op = reinterpret_cast<float4*>(outM + (size_t)l * LS + moff);
#pragma unroll
        for (int p = 0; p < 2; p++) {
            float4 o;
            o.x = omg * m[l][p].x + gh * (m[up][p].x + m[dn][p].x) + eu * vv[p].x;
            o.y = omg * m[l][p].y + gh * (m[up][p].y + m[dn][p].y) + eu * vv[p].y;
            o.z = omg * m[l][p].z + gh * (m[up][p].z + m[dn][p].z) + eu * vv[p].z;
            o.w = omg * m[l][p].w + gh * (m[up][p].w + m[dn][p].w) + eu * vv[p].w;
            __stcs(op + p, o);
        }
    }
}

// ---------------------------------------------------------------------------
extern "C" void kernel_launch(void* const* d_in, const int* in_sizes, int n_in,
                              void* d_out, int out_size)
{
    const float* x        = (const float*)d_in[0];
    const float* c        = (const float*)d_in[1];
    const float* h        = (const float*)d_in[2];
    const float* M        = (const float*)d_in[3];
    const float* phi_w    = (const float*)d_in[4];
    const float* phi_b    = (const float*)d_in[5];
    const float* alpha_w  = (const float*)d_in[6];
    const float* alpha_b  = (const float*)d_in[7];
    const float* beta_w   = (const float*)d_in[8];
    const float* beta_b   = (const float*)d_in[9];
    const float* u_w      = (const float*)d_in[10];
    const float* u_b      = (const float*)d_in[11];
    const float* v_w      = (const float*)d_in[12];
    const float* v_b      = (const float*)d_in[13];
    const float* gamma_l  = (const float*)d_in[14];
    const float* eta_l    = (const float*)d_in[15];
    float* out = (float*)d_out;

    gemm_gate<<<dim3(24, 4, KSPLIT), 256>>>(x, c, h, phi_w, alpha_w, beta_w);
    gate_epi<<<256, 256>>>(h, phi_b, alpha_b, beta_b, out);
    gemm_uv<<<dim3(16, 4, KSPLIT), 256>>>(out, x, c, u_w, v_w);
    uv_reduce<<<256, 256>>>();
    m_update<<<4096, 256>>>(M, u_b, v_b, gamma_l, eta_l, out);
}